// round 13
// baseline (speedup 1.0000x reference)
#include <cuda_runtime.h>
#include <cuda_fp16.h>
#include <cstdint>

#define B_    2
#define S_    2048
#define HID_  4096
#define NH_   32
#define NKV_  8
#define HD_   128
#define MROWS (B_ * S_)     // 4096
#define WIN_  1024

// Scratch (allocation-free: __device__ globals), fp16 — ~200 MB total
__device__ __half g_Hh[(size_t)MROWS * HID_];        // 32 MB hidden fp16
__device__ __half g_Wq[(size_t)HID_ * HID_];         // 32 MB [N][K]
__device__ __half g_Wk[(size_t)(NKV_ * HD_) * HID_]; // 8 MB
__device__ __half g_Wv[(size_t)(NKV_ * HD_) * HID_]; // 8 MB
__device__ __half g_Wo[(size_t)HID_ * HID_];         // 32 MB
__device__ __half g_Q [(size_t)MROWS * NH_ * HD_];   // 32 MB
__device__ __half g_K [(size_t)MROWS * NKV_ * HD_];  // 8 MB
__device__ __half g_V [(size_t)MROWS * NKV_ * HD_];  // 8 MB
__device__ __half g_Vt[(size_t)B_ * NKV_ * HD_ * S_];// 8 MB  [b][kvh][hd][s]
__device__ __half g_AO[(size_t)MROWS * NH_ * HD_];   // 32 MB

__device__ __forceinline__ void mma_f16(
    float* c, unsigned a0, unsigned a1, unsigned a2, unsigned a3,
    unsigned b0, unsigned b1)
{
    asm volatile(
        "mma.sync.aligned.m16n8k16.row.col.f32.f16.f16.f32 "
        "{%0,%1,%2,%3}, {%4,%5,%6,%7}, {%8,%9}, {%0,%1,%2,%3};\n"
        : "+f"(c[0]), "+f"(c[1]), "+f"(c[2]), "+f"(c[3])
        : "r"(a0), "r"(a1), "r"(a2), "r"(a3), "r"(b0), "r"(b1));
}

__device__ __forceinline__ unsigned ldu32(const __half* p) {
    return *reinterpret_cast<const unsigned*>(p);
}

// epilogue pair-store: fp32 or fp16 C
__device__ __forceinline__ void stpair(float* C, size_t idx, float a, float b) {
    *(float2*)(C + idx) = make_float2(a, b);
}
__device__ __forceinline__ void stpair(__half* C, size_t idx, float a, float b) {
    *(__half2*)(C + idx) = __floats2half2_rn(a, b);
}

// ===========================================================================
// FP16 tensor-core GEMM: C[M,N] = A[M,K] @ Bt[N,K]^T   (both fp16, K-contig)
// 128x128 tile, BK=64, 256 threads (8 warps), warp tile 64x32, m16n8k16.
// Smem rows stride 72 halfs -> fragment LDS bank == lane (conflict-free).
// ===========================================================================
#define HSTR 72
#define HSZ  (128 * HSTR)          // 9216 halfs per tile
#define HGEMM_SMEM (4 * HSZ * 2)   // 73728 B (A x2, B x2)

template <typename CT>
__global__ __launch_bounds__(256) void h16_gemm(
    const __half* __restrict__ A, const __half* __restrict__ Bt,
    CT* __restrict__ C, int M, int N, int K)
{
    extern __shared__ __align__(16) __half sh[];
    __half* As = sh;              // 2 x HSZ
    __half* Bs = sh + 2 * HSZ;    // 2 x HSZ

    const int t    = threadIdx.x;
    const int warp = t >> 5;
    const int lane = t & 31;
    const int r    = lane >> 2;
    const int c    = lane & 3;
    const int wm   = (warp >> 2) * 64;
    const int wn   = (warp & 3) * 32;
    const int bm   = blockIdx.y * 128;
    const int bn   = blockIdx.x * 128;

    // loader mapping: 128 rows x 8 uint4-chunks (64 halfs/row), 4 iters
    const uint4* agp[4];
    const uint4* bgp[4];
    int soff[4];
    #pragma unroll
    for (int i = 0; i < 4; i++) {
        int lin = t + i * 256;
        int row = lin >> 3, ch = lin & 7;
        agp[i] = (const uint4*)(A  + (size_t)(bm + row) * K) + ch;
        bgp[i] = (const uint4*)(Bt + (size_t)(bn + row) * K) + ch;
        soff[i] = row * HSTR + ch * 8;
    }

    const int NKT = K / 64;
    uint4 ra[4], rb[4];

    #pragma unroll
    for (int i = 0; i < 4; i++) { ra[i] = agp[i][0]; rb[i] = bgp[i][0]; }
    #pragma unroll
    for (int i = 0; i < 4; i++) {
        *(uint4*)&As[soff[i]] = ra[i];
        *(uint4*)&Bs[soff[i]] = rb[i];
    }
    __syncthreads();

    float acc[4][4][4];
    #pragma unroll
    for (int mt = 0; mt < 4; mt++)
        #pragma unroll
        for (int nt = 0; nt < 4; nt++)
            #pragma unroll
            for (int x = 0; x < 4; x++) acc[mt][nt][x] = 0.f;

    for (int kt = 0; kt < NKT; kt++) {
        if (kt + 1 < NKT) {
            #pragma unroll
            for (int i = 0; i < 4; i++) {
                ra[i] = agp[i][(kt + 1) * 8];
                rb[i] = bgp[i][(kt + 1) * 8];
            }
        }

        const __half* Ab = As + (kt & 1) * HSZ;
        const __half* Bb = Bs + (kt & 1) * HSZ;

        #pragma unroll
        for (int ks = 0; ks < 4; ks++) {
            unsigned af[4][4], bf[4][2];
            #pragma unroll
            for (int mt = 0; mt < 4; mt++) {
                const __half* p = Ab + (wm + mt * 16 + r) * HSTR + ks * 16 + 2 * c;
                af[mt][0] = ldu32(p);
                af[mt][1] = ldu32(p + 8 * HSTR);
                af[mt][2] = ldu32(p + 8);
                af[mt][3] = ldu32(p + 8 * HSTR + 8);
            }
            #pragma unroll
            for (int nt = 0; nt < 4; nt++) {
                const __half* p = Bb + (wn + nt * 8 + r) * HSTR + ks * 16 + 2 * c;
                bf[nt][0] = ldu32(p);
                bf[nt][1] = ldu32(p + 8);
            }
            #pragma unroll
            for (int mt = 0; mt < 4; mt++)
                #pragma unroll
                for (int nt = 0; nt < 4; nt++)
                    mma_f16(acc[mt][nt], af[mt][0], af[mt][1], af[mt][2], af[mt][3],
                            bf[nt][0], bf[nt][1]);
        }

        if (kt + 1 < NKT) {
            __half* Abn = As + ((kt + 1) & 1) * HSZ;
            __half* Bbn = Bs + ((kt + 1) & 1) * HSZ;
            #pragma unroll
            for (int i = 0; i < 4; i++) {
                *(uint4*)&Abn[soff[i]] = ra[i];
                *(uint4*)&Bbn[soff[i]] = rb[i];
            }
        }
        __syncthreads();
    }

    #pragma unroll
    for (int mt = 0; mt < 4; mt++) {
        const int row0 = bm + wm + mt * 16 + r;
        #pragma unroll
        for (int nt = 0; nt < 4; nt++) {
            const int col = bn + wn + nt * 8 + 2 * c;
            stpair(C, (size_t)row0 * N + col,       acc[mt][nt][0], acc[mt][nt][1]);
            stpair(C, (size_t)(row0 + 8) * N + col, acc[mt][nt][2], acc[mt][nt][3]);
        }
    }
}

// ===========================================================================
// Prep kernels
// ===========================================================================
__global__ void cvt_h(const float* __restrict__ src, __half* __restrict__ dst)
{
    size_t i = (size_t)blockIdx.x * blockDim.x + threadIdx.x;
    float4 v = *(const float4*)(src + i * 4);
    __half2 h0 = __floats2half2_rn(v.x, v.y);
    __half2 h1 = __floats2half2_rn(v.z, v.w);
    uint2 o;
    o.x = *reinterpret_cast<unsigned*>(&h0);
    o.y = *reinterpret_cast<unsigned*>(&h1);
    *(uint2*)(dst + i * 4) = o;
}

// src [K][N] fp32 -> dst [N][K] fp16
__global__ void transpose_h(const float* __restrict__ src, __half* __restrict__ dst,
                            int K, int N)
{
    __shared__ float tile[32][33];
    int x = blockIdx.x * 32 + threadIdx.x;   // n
    int y = blockIdx.y * 32 + threadIdx.y;   // k
    #pragma unroll
    for (int i = 0; i < 32; i += 8)
        tile[threadIdx.y + i][threadIdx.x] = src[(size_t)(y + i) * N + x];
    __syncthreads();
    int x2 = blockIdx.y * 32 + threadIdx.x;  // k
    int y2 = blockIdx.x * 32 + threadIdx.y;  // n
    #pragma unroll
    for (int i = 0; i < 32; i += 8)
        dst[(size_t)(y2 + i) * K + x2] = __float2half_rn(tile[threadIdx.x][threadIdx.y + i]);
}

// g_V [m][kvh*HD+hd] -> g_Vt [b][kvh][hd][s]
__global__ void vtrans_h()
{
    __shared__ __half tile[32][33];
    int b   = blockIdx.z >> 3;
    int kvh = blockIdx.z & 7;
    int x = blockIdx.y * 32 + threadIdx.x;   // hd
    int y = blockIdx.x * 32 + threadIdx.y;   // s
    #pragma unroll
    for (int i = 0; i < 32; i += 8)
        tile[threadIdx.y + i][threadIdx.x] =
            g_V[(size_t)(b * S_ + y + i) * (NKV_ * HD_) + kvh * HD_ + x];
    __syncthreads();
    int x2 = blockIdx.x * 32 + threadIdx.x;  // s
    int y2 = blockIdx.y * 32 + threadIdx.y;  // hd
    #pragma unroll
    for (int i = 0; i < 32; i += 8)
        g_Vt[((size_t)(b * NKV_ + kvh) * HD_ + y2 + i) * S_ + x2] =
            tile[threadIdx.x][threadIdx.y + i];
}

// RoPE in-place on fp16 g_Q, g_K. One thread per half2 pair (2p,2p+1 | +64).
__global__ void rope_h(const int* __restrict__ pos_ids)
{
    const int QP = MROWS * NH_ * 32;    // 4194304
    const int KP = MROWS * NKV_ * 32;   // 1048576
    int idx = blockIdx.x * blockDim.x + threadIdx.x;
    if (idx >= QP + KP) return;

    __half* base;
    int m, p;
    if (idx < QP) {
        m = idx >> 10;
        int rem = idx & 1023;
        base = g_Q + ((size_t)m * NH_ + (rem >> 5)) * HD_;
        p = rem & 31;
    } else {
        int i2 = idx - QP;
        m = i2 >> 8;
        int rem = i2 & 255;
        base = g_K + ((size_t)m * NKV_ + (rem >> 5)) * HD_;
        p = rem & 31;
    }
    float pos = (float)pos_ids[m];
    float i0 = exp2f((float)(2 * p)     * -0.20762050593045857f);
    float i1 = exp2f((float)(2 * p + 1) * -0.20762050593045857f);
    float s0, c0, s1, c1;
    sincosf(pos * i0, &s0, &c0);
    sincosf(pos * i1, &s1, &c1);

    __half2 lo = *(__half2*)(base + 2 * p);
    __half2 hi = *(__half2*)(base + 64 + 2 * p);
    float x00 = __low2float(lo),  x01 = __high2float(lo);
    float x10 = __low2float(hi),  x11 = __high2float(hi);
    *(__half2*)(base + 2 * p)      = __floats2half2_rn(x00 * c0 - x10 * s0,
                                                       x01 * c1 - x11 * s1);
    *(__half2*)(base + 64 + 2 * p) = __floats2half2_rn(x10 * c0 + x00 * s0,
                                                       x11 * c1 + x01 * s1);
}

// ===========================================================================
// FP16 tensor-core flash attention, sliding window 1024, GQA.
// Block = (q_tile 128, head, batch), 256 threads (8 warps x 16 q-rows).
// Qs/Ks [row][136h], Vs [hd][72h], Ps per-warp [16][72h] — all frag LDS
// bank-conflict-free (bank == 4r+c == lane).
// ===========================================================================
#define AQSTR 136
#define AVSTR 72
#define APSTR 72
#define QT_ 128
#define MASKED_ (-30000.0f)
#define MINIT_  (-10000.0f)
#define ATTN_SMEM ((128*AQSTR + 64*AQSTR + 128*AVSTR + 8*16*APSTR) * 2) // 89088 B

__global__ __launch_bounds__(256) void attn_mma_kernel()
{
    extern __shared__ __align__(16) __half sm[];
    __half* Qs = sm;                           // 128*136 = 17408 h
    __half* Ks = sm + 128 * AQSTR;             // 64*136  = 8704 h
    __half* Vs = Ks + 64 * AQSTR;              // 128*72  = 9216 h
    __half* Ps = Vs + 128 * AVSTR;             // 8*16*72 = 9216 h

    const int t     = threadIdx.x;
    const int w     = t >> 5;
    const int lane  = t & 31;
    const int r     = lane >> 2;
    const int c     = lane & 3;
    const int qtile = (int)gridDim.x - 1 - (int)blockIdx.x;   // heavy tiles first
    const int h     = blockIdx.y;
    const int b     = blockIdx.z;
    const int q0    = qtile * QT_;
    const int kvh   = h >> 2;

    __half* Psw = Ps + w * (16 * APSTR);

    // ---- load Q tile ----
    {
        const uint4* Qg4 = (const uint4*)(g_Q + ((size_t)(b * S_ + q0) * NH_ + h) * HD_);
        #pragma unroll
        for (int i = 0; i < 8; i++) {
            int lin = t + i * 256;
            int row = lin >> 4, ch = lin & 15;
            *(uint4*)&Qs[row * AQSTR + ch * 8] = Qg4[row * (NH_ * HD_ / 8) + ch];
        }
    }

    float m0 = MINIT_, m1 = MINIT_, l0 = 0.f, l1 = 0.f;
    float acc[16][4];
    #pragma unroll
    for (int nt = 0; nt < 16; nt++)
        #pragma unroll
        for (int x = 0; x < 4; x++) acc[nt][x] = 0.f;

    const int gi0 = q0 + w * 16 + r;
    const int gi1 = gi0 + 8;
    const int kb_lo = (q0 >= WIN_) ? ((q0 - WIN_) >> 6) : 0;
    const int kb_hi = (q0 + QT_ - 1) >> 6;
    const float scale = 0.08838834764831845f;   // 1/sqrt(128)

    for (int kb = kb_lo; kb <= kb_hi; kb++) {
        __syncthreads();
        // ---- load K (64x128) and V^T (128 hd x 64 keys) ----
        {
            const uint4* Kg4 = (const uint4*)(g_K +
                ((size_t)(b * S_ + kb * 64) * NKV_ + kvh) * HD_);
            const uint4* Vg4 = (const uint4*)(g_Vt +
                ((size_t)(b * NKV_ + kvh) * HD_) * S_ + kb * 64);
            #pragma unroll
            for (int i = 0; i < 4; i++) {
                int lin = t + i * 256;
                int row = lin >> 4, ch = lin & 15;
                *(uint4*)&Ks[row * AQSTR + ch * 8] = Kg4[row * (NKV_ * HD_ / 8) + ch];
                int vrow = lin >> 3, vch = lin & 7;
                *(uint4*)&Vs[vrow * AVSTR + vch * 8] = Vg4[vrow * (S_ / 8) + vch];
            }
        }
        __syncthreads();

        // ---- S = Q @ K^T : per warp 16x64, 8 k-steps of 16 ----
        float s[8][4];
        #pragma unroll
        for (int nt = 0; nt < 8; nt++)
            #pragma unroll
            for (int x = 0; x < 4; x++) s[nt][x] = 0.f;

        #pragma unroll
        for (int ks = 0; ks < 8; ks++) {
            const __half* qp = Qs + (w * 16 + r) * AQSTR + ks * 16 + 2 * c;
            unsigned a0 = ldu32(qp);
            unsigned a1 = ldu32(qp + 8 * AQSTR);
            unsigned a2 = ldu32(qp + 8);
            unsigned a3 = ldu32(qp + 8 * AQSTR + 8);
            #pragma unroll
            for (int nt = 0; nt < 8; nt++) {
                const __half* kp = Ks + (nt * 8 + r) * AQSTR + ks * 16 + 2 * c;
                mma_f16(s[nt], a0, a1, a2, a3, ldu32(kp), ldu32(kp + 8));
            }
        }

        // ---- scale + window mask + row max ----
        float mx0 = MASKED_, mx1 = MASKED_;
        #pragma unroll
        for (int nt = 0; nt < 8; nt++) {
            #pragma unroll
            for (int jj = 0; jj < 2; jj++) {
                int gj = kb * 64 + nt * 8 + 2 * c + jj;
                float v0 = s[nt][jj] * scale;
                v0 = (gj <= gi0 && gj + WIN_ >= gi0) ? v0 : MASKED_;
                s[nt][jj] = v0;
                mx0 = fmaxf(mx0, v0);
                float v1 = s[nt][2 + jj] * scale;
                v1 = (gj <= gi1 && gj + WIN_ >= gi1) ? v1 : MASKED_;
                s[nt][2 + jj] = v1;
                mx1 = fmaxf(mx1, v1);
            }
        }
        mx0 = fmaxf(mx0, __shfl_xor_sync(0xffffffffu, mx0, 1));
        mx0 = fmaxf(mx0, __shfl_xor_sync(0xffffffffu, mx0, 2));
        mx1 = fmaxf(mx1, __shfl_xor_sync(0xffffffffu, mx1, 1));
        mx1 = fmaxf(mx1, __shfl_xor_sync(0xffffffffu, mx1, 2));

        const float mn0 = fmaxf(m0, mx0);
        const float mn1 = fmaxf(m1, mx1);
        const float al0 = __expf(m0 - mn0);
        const float al1 = __expf(m1 - mn1);
        m0 = mn0; m1 = mn1;
        l0 *= al0; l1 *= al1;
        #pragma unroll
        for (int nt = 0; nt < 16; nt++) {
            acc[nt][0] *= al0; acc[nt][1] *= al0;
            acc[nt][2] *= al1; acc[nt][3] *= al1;
        }

        // ---- exp + fp16 P to per-warp smem ----
        float ss0 = 0.f, ss1 = 0.f;
        #pragma unroll
        for (int nt = 0; nt < 8; nt++) {
            __half2 h01 = __floats2half2_rn(__expf(s[nt][0] - mn0),
                                            __expf(s[nt][1] - mn0));
            __half2 h23 = __floats2half2_rn(__expf(s[nt][2] - mn1),
                                            __expf(s[nt][3] - mn1));
            ss0 += __low2float(h01) + __high2float(h01);
            ss1 += __low2float(h23) + __high2float(h23);
            *(__half2*)&Psw[r * APSTR + nt * 8 + 2 * c]       = h01;
            *(__half2*)&Psw[(r + 8) * APSTR + nt * 8 + 2 * c] = h23;
        }
        ss0 += __shfl_xor_sync(0xffffffffu, ss0, 1);
        ss0 += __shfl_xor_sync(0xffffffffu, ss0, 2);
        ss1 += __shfl_xor_sync(0xffffffffu, ss1, 1);
        ss1 += __shfl_xor_sync(0xffffffffu, ss1, 2);
        l0 += ss0; l1 += ss1;

        __syncwarp();

        // ---- O += P @ V : 16 n-tiles x 4 k-steps of 16 ----
        #pragma unroll
        for (int ks = 0; ks < 4; ks++) {
            const __half* pp = Psw + r * APSTR + ks * 16 + 2 * c;
            unsigned a0 = ldu32(pp);
            unsigned a1 = ldu32(pp + 8 * APSTR);
            unsigned a2 = ldu32(pp + 8);
            unsigned a3 = ldu32(pp + 8 * APSTR + 8);
            #pragma unroll
            for (int nt = 0; nt < 16; nt++) {
                const __half* vp = Vs + (nt * 8 + r) * AVSTR + ks * 16 + 2 * c;
                mma_f16(acc[nt], a0, a1, a2, a3, ldu32(vp), ldu32(vp + 8));
            }
        }
    }

    // ---- epilogue: normalized fp16 AO ----
    const float il0 = 1.f / l0;
    const float il1 = 1.f / l1;
    __half* O0 = g_AO + ((size_t)(b * S_ + gi0) * NH_ + h) * HD_;
    __half* O1 = g_AO + ((size_t)(b * S_ + gi1) * NH_ + h) * HD_;
    #pragma unroll
    for (int nt = 0; nt < 16; nt++) {
        int col = nt * 8 + 2 * c;
        *(__half2*)(O0 + col) = __floats2half2_rn(acc[nt][0] * il0, acc[nt][1] * il0);
        *(__half2*)(O1 + col) = __floats2half2_rn(acc[nt][2] * il1, acc[nt][3] * il1);
    }
}

// ===========================================================================
extern "C" void kernel_launch(void* const* d_in, const int* in_sizes, int n_in,
                              void* d_out, int out_size)
{
    (void)in_sizes; (void)n_in; (void)out_size;
    const float* hidden  = (const float*)d_in[0];
    const int*   pos_ids = (const int*)d_in[2];
    const float* q_w     = (const float*)d_in[3];
    const float* k_w     = (const float*)d_in[4];
    const float* v_w     = (const float*)d_in[5];
    const float* o_w     = (const float*)d_in[6];
    float* out = (float*)d_out;

    __half *Hh, *Wq, *Wk, *Wv, *Wo, *Qh, *Kh, *Vh, *AOh;
    cudaGetSymbolAddress((void**)&Hh,  g_Hh);
    cudaGetSymbolAddress((void**)&Wq,  g_Wq);
    cudaGetSymbolAddress((void**)&Wk,  g_Wk);
    cudaGetSymbolAddress((void**)&Wv,  g_Wv);
    cudaGetSymbolAddress((void**)&Wo,  g_Wo);
    cudaGetSymbolAddress((void**)&Qh,  g_Q);
    cudaGetSymbolAddress((void**)&Kh,  g_K);
    cudaGetSymbolAddress((void**)&Vh,  g_V);
    cudaGetSymbolAddress((void**)&AOh, g_AO);

    cudaFuncSetAttribute(h16_gemm<__half>,
        cudaFuncAttributeMaxDynamicSharedMemorySize, HGEMM_SMEM);
    cudaFuncSetAttribute(h16_gemm<float>,
        cudaFuncAttributeMaxDynamicSharedMemorySize, HGEMM_SMEM);
    cudaFuncSetAttribute(attn_mma_kernel,
        cudaFuncAttributeMaxDynamicSharedMemorySize, ATTN_SMEM);

    // Prep: fp16 conversions + weight transposes
    cvt_h<<<(MROWS * HID_ / 4) / 256, 256>>>(hidden, Hh);
    transpose_h<<<dim3(HID_ / 32, HID_ / 32), dim3(32, 8)>>>(q_w, Wq, HID_, HID_);
    transpose_h<<<dim3((NKV_ * HD_) / 32, HID_ / 32), dim3(32, 8)>>>(k_w, Wk, HID_, NKV_ * HD_);
    transpose_h<<<dim3((NKV_ * HD_) / 32, HID_ / 32), dim3(32, 8)>>>(v_w, Wv, HID_, NKV_ * HD_);
    transpose_h<<<dim3(HID_ / 32, HID_ / 32), dim3(32, 8)>>>(o_w, Wo, HID_, HID_);

    // QKV projections (fp16 in/out, fp32 accum)
    h16_gemm<__half><<<dim3(NH_ * HD_ / 128, MROWS / 128), 256, HGEMM_SMEM>>>(
        Hh, Wq, Qh, MROWS, NH_ * HD_, HID_);
    h16_gemm<__half><<<dim3(NKV_ * HD_ / 128, MROWS / 128), 256, HGEMM_SMEM>>>(
        Hh, Wk, Kh, MROWS, NKV_ * HD_, HID_);
    h16_gemm<__half><<<dim3(NKV_ * HD_ / 128, MROWS / 128), 256, HGEMM_SMEM>>>(
        Hh, Wv, Vh, MROWS, NKV_ * HD_, HID_);

    // RoPE (fp16 in-place) + V transpose
    {
        int total = MROWS * NH_ * 32 + MROWS * NKV_ * 32;
        rope_h<<<(total + 255) / 256, 256>>>(pos_ids);
    }
    vtrans_h<<<dim3(S_ / 32, HD_ / 32, B_ * NKV_), dim3(32, 8)>>>();

    // Attention
    attn_mma_kernel<<<dim3(S_ / QT_, NH_, B_), 256, ATTN_SMEM>>>();

    // Output projection (fp16 A/B, fp32 out)
    h16_gemm<float><<<dim3(HID_ / 128, MROWS / 128), 256, HGEMM_SMEM>>>(
        AOh, Wo, out, MROWS, HID_, HID_);
}

// round 14
// speedup vs baseline: 1.0001x; 1.0001x over previous
#include <cuda_runtime.h>
#include <cuda_fp16.h>
#include <cstdint>

#define B_    2
#define S_    2048
#define HID_  4096
#define NH_   32
#define NKV_  8
#define HD_   128
#define MROWS (B_ * S_)     // 4096
#define WIN_  1024

// Scratch (allocation-free: __device__ globals), fp16 — ~200 MB total
__device__ __half g_Hh[(size_t)MROWS * HID_];        // 32 MB hidden fp16
__device__ __half g_Wq[(size_t)HID_ * HID_];         // 32 MB [N][K]
__device__ __half g_Wk[(size_t)(NKV_ * HD_) * HID_]; // 8 MB
__device__ __half g_Wv[(size_t)(NKV_ * HD_) * HID_]; // 8 MB
__device__ __half g_Wo[(size_t)HID_ * HID_];         // 32 MB
__device__ __half g_Q [(size_t)MROWS * NH_ * HD_];   // 32 MB
__device__ __half g_K [(size_t)MROWS * NKV_ * HD_];  // 8 MB
__device__ __half g_V [(size_t)MROWS * NKV_ * HD_];  // 8 MB
__device__ __half g_Vt[(size_t)B_ * NKV_ * HD_ * S_];// 8 MB  [b][kvh][hd][s]
__device__ __half g_AO[(size_t)MROWS * NH_ * HD_];   // 32 MB

__device__ __forceinline__ void mma_f16(
    float* c, unsigned a0, unsigned a1, unsigned a2, unsigned a3,
    unsigned b0, unsigned b1)
{
    asm volatile(
        "mma.sync.aligned.m16n8k16.row.col.f32.f16.f16.f32 "
        "{%0,%1,%2,%3}, {%4,%5,%6,%7}, {%8,%9}, {%0,%1,%2,%3};\n"
        : "+f"(c[0]), "+f"(c[1]), "+f"(c[2]), "+f"(c[3])
        : "r"(a0), "r"(a1), "r"(a2), "r"(a3), "r"(b0), "r"(b1));
}

__device__ __forceinline__ unsigned ldu32(const __half* p) {
    return *reinterpret_cast<const unsigned*>(p);
}

// epilogue pair-store: fp32 or fp16 C
__device__ __forceinline__ void stpair(float* C, size_t idx, float a, float b) {
    *(float2*)(C + idx) = make_float2(a, b);
}
__device__ __forceinline__ void stpair(__half* C, size_t idx, float a, float b) {
    *(__half2*)(C + idx) = __floats2half2_rn(a, b);
}

// ===========================================================================
// FP16 tensor-core GEMM: C[M,N] = A[M,K] @ Bt[N,K]^T   (both fp16, K-contig)
// 128x128 tile, BK=64, 256 threads (8 warps), warp tile 64x32, m16n8k16.
// Smem rows stride 72 halfs -> fragment LDS bank == lane (conflict-free).
// ===========================================================================
#define HSTR 72
#define HSZ  (128 * HSTR)          // 9216 halfs per tile
#define HGEMM_SMEM (4 * HSZ * 2)   // 73728 B (A x2, B x2)

template <typename CT>
__global__ __launch_bounds__(256) void h16_gemm(
    const __half* __restrict__ A, const __half* __restrict__ Bt,
    CT* __restrict__ C, int M, int N, int K)
{
    extern __shared__ __align__(16) __half sh[];
    __half* As = sh;              // 2 x HSZ
    __half* Bs = sh + 2 * HSZ;    // 2 x HSZ

    const int t    = threadIdx.x;
    const int warp = t >> 5;
    const int lane = t & 31;
    const int r    = lane >> 2;
    const int c    = lane & 3;
    const int wm   = (warp >> 2) * 64;
    const int wn   = (warp & 3) * 32;
    const int bm   = blockIdx.y * 128;
    const int bn   = blockIdx.x * 128;

    // loader mapping: 128 rows x 8 uint4-chunks (64 halfs/row), 4 iters
    const uint4* agp[4];
    const uint4* bgp[4];
    int soff[4];
    #pragma unroll
    for (int i = 0; i < 4; i++) {
        int lin = t + i * 256;
        int row = lin >> 3, ch = lin & 7;
        agp[i] = (const uint4*)(A  + (size_t)(bm + row) * K) + ch;
        bgp[i] = (const uint4*)(Bt + (size_t)(bn + row) * K) + ch;
        soff[i] = row * HSTR + ch * 8;
    }

    const int NKT = K / 64;
    uint4 ra[4], rb[4];

    #pragma unroll
    for (int i = 0; i < 4; i++) { ra[i] = agp[i][0]; rb[i] = bgp[i][0]; }
    #pragma unroll
    for (int i = 0; i < 4; i++) {
        *(uint4*)&As[soff[i]] = ra[i];
        *(uint4*)&Bs[soff[i]] = rb[i];
    }
    __syncthreads();

    float acc[4][4][4];
    #pragma unroll
    for (int mt = 0; mt < 4; mt++)
        #pragma unroll
        for (int nt = 0; nt < 4; nt++)
            #pragma unroll
            for (int x = 0; x < 4; x++) acc[mt][nt][x] = 0.f;

    for (int kt = 0; kt < NKT; kt++) {
        if (kt + 1 < NKT) {
            #pragma unroll
            for (int i = 0; i < 4; i++) {
                ra[i] = agp[i][(kt + 1) * 8];
                rb[i] = bgp[i][(kt + 1) * 8];
            }
        }

        const __half* Ab = As + (kt & 1) * HSZ;
        const __half* Bb = Bs + (kt & 1) * HSZ;

        #pragma unroll
        for (int ks = 0; ks < 4; ks++) {
            unsigned af[4][4], bf[4][2];
            #pragma unroll
            for (int mt = 0; mt < 4; mt++) {
                const __half* p = Ab + (wm + mt * 16 + r) * HSTR + ks * 16 + 2 * c;
                af[mt][0] = ldu32(p);
                af[mt][1] = ldu32(p + 8 * HSTR);
                af[mt][2] = ldu32(p + 8);
                af[mt][3] = ldu32(p + 8 * HSTR + 8);
            }
            #pragma unroll
            for (int nt = 0; nt < 4; nt++) {
                const __half* p = Bb + (wn + nt * 8 + r) * HSTR + ks * 16 + 2 * c;
                bf[nt][0] = ldu32(p);
                bf[nt][1] = ldu32(p + 8);
            }
            #pragma unroll
            for (int mt = 0; mt < 4; mt++)
                #pragma unroll
                for (int nt = 0; nt < 4; nt++)
                    mma_f16(acc[mt][nt], af[mt][0], af[mt][1], af[mt][2], af[mt][3],
                            bf[nt][0], bf[nt][1]);
        }

        if (kt + 1 < NKT) {
            __half* Abn = As + ((kt + 1) & 1) * HSZ;
            __half* Bbn = Bs + ((kt + 1) & 1) * HSZ;
            #pragma unroll
            for (int i = 0; i < 4; i++) {
                *(uint4*)&Abn[soff[i]] = ra[i];
                *(uint4*)&Bbn[soff[i]] = rb[i];
            }
        }
        __syncthreads();
    }

    #pragma unroll
    for (int mt = 0; mt < 4; mt++) {
        const int row0 = bm + wm + mt * 16 + r;
        #pragma unroll
        for (int nt = 0; nt < 4; nt++) {
            const int col = bn + wn + nt * 8 + 2 * c;
            stpair(C, (size_t)row0 * N + col,       acc[mt][nt][0], acc[mt][nt][1]);
            stpair(C, (size_t)(row0 + 8) * N + col, acc[mt][nt][2], acc[mt][nt][3]);
        }
    }
}

// ===========================================================================
// Prep kernels
// ===========================================================================
__global__ void cvt_h(const float* __restrict__ src, __half* __restrict__ dst)
{
    size_t i = (size_t)blockIdx.x * blockDim.x + threadIdx.x;
    float4 v = *(const float4*)(src + i * 4);
    __half2 h0 = __floats2half2_rn(v.x, v.y);
    __half2 h1 = __floats2half2_rn(v.z, v.w);
    uint2 o;
    o.x = *reinterpret_cast<unsigned*>(&h0);
    o.y = *reinterpret_cast<unsigned*>(&h1);
    *(uint2*)(dst + i * 4) = o;
}

// src [K][N] fp32 -> dst [N][K] fp16
__global__ void transpose_h(const float* __restrict__ src, __half* __restrict__ dst,
                            int K, int N)
{
    __shared__ float tile[32][33];
    int x = blockIdx.x * 32 + threadIdx.x;   // n
    int y = blockIdx.y * 32 + threadIdx.y;   // k
    #pragma unroll
    for (int i = 0; i < 32; i += 8)
        tile[threadIdx.y + i][threadIdx.x] = src[(size_t)(y + i) * N + x];
    __syncthreads();
    int x2 = blockIdx.y * 32 + threadIdx.x;  // k
    int y2 = blockIdx.x * 32 + threadIdx.y;  // n
    #pragma unroll
    for (int i = 0; i < 32; i += 8)
        dst[(size_t)(y2 + i) * K + x2] = __float2half_rn(tile[threadIdx.x][threadIdx.y + i]);
}

// g_V [m][kvh*HD+hd] -> g_Vt [b][kvh][hd][s]
__global__ void vtrans_h()
{
    __shared__ __half tile[32][33];
    int b   = blockIdx.z >> 3;
    int kvh = blockIdx.z & 7;
    int x = blockIdx.y * 32 + threadIdx.x;   // hd
    int y = blockIdx.x * 32 + threadIdx.y;   // s
    #pragma unroll
    for (int i = 0; i < 32; i += 8)
        tile[threadIdx.y + i][threadIdx.x] =
            g_V[(size_t)(b * S_ + y + i) * (NKV_ * HD_) + kvh * HD_ + x];
    __syncthreads();
    int x2 = blockIdx.x * 32 + threadIdx.x;  // s
    int y2 = blockIdx.y * 32 + threadIdx.y;  // hd
    #pragma unroll
    for (int i = 0; i < 32; i += 8)
        g_Vt[((size_t)(b * NKV_ + kvh) * HD_ + y2 + i) * S_ + x2] =
            tile[threadIdx.x][threadIdx.y + i];
}

// RoPE in-place on fp16 g_Q, g_K. One thread per half2 pair (2p,2p+1 | +64).
__global__ void rope_h(const int* __restrict__ pos_ids)
{
    const int QP = MROWS * NH_ * 32;    // 4194304
    const int KP = MROWS * NKV_ * 32;   // 1048576
    int idx = blockIdx.x * blockDim.x + threadIdx.x;
    if (idx >= QP + KP) return;

    __half* base;
    int m, p;
    if (idx < QP) {
        m = idx >> 10;
        int rem = idx & 1023;
        base = g_Q + ((size_t)m * NH_ + (rem >> 5)) * HD_;
        p = rem & 31;
    } else {
        int i2 = idx - QP;
        m = i2 >> 8;
        int rem = i2 & 255;
        base = g_K + ((size_t)m * NKV_ + (rem >> 5)) * HD_;
        p = rem & 31;
    }
    float pos = (float)pos_ids[m];
    float i0 = exp2f((float)(2 * p)     * -0.20762050593045857f);
    float i1 = exp2f((float)(2 * p + 1) * -0.20762050593045857f);
    float s0, c0, s1, c1;
    sincosf(pos * i0, &s0, &c0);
    sincosf(pos * i1, &s1, &c1);

    __half2 lo = *(__half2*)(base + 2 * p);
    __half2 hi = *(__half2*)(base + 64 + 2 * p);
    float x00 = __low2float(lo),  x01 = __high2float(lo);
    float x10 = __low2float(hi),  x11 = __high2float(hi);
    *(__half2*)(base + 2 * p)      = __floats2half2_rn(x00 * c0 - x10 * s0,
                                                       x01 * c1 - x11 * s1);
    *(__half2*)(base + 64 + 2 * p) = __floats2half2_rn(x10 * c0 + x00 * s0,
                                                       x11 * c1 + x01 * s1);
}

// ===========================================================================
// FP16 tensor-core flash attention, sliding window 1024, GQA.
// Block = (q_tile 128, head, batch), 256 threads (8 warps x 16 q-rows).
// Qs/Ks [row][136h], Vs [hd][72h], Ps per-warp [16][72h] — all frag LDS
// bank-conflict-free (bank == 4r+c == lane).
// ===========================================================================
#define AQSTR 136
#define AVSTR 72
#define APSTR 72
#define QT_ 128
#define MASKED_ (-30000.0f)
#define MINIT_  (-10000.0f)
#define ATTN_SMEM ((128*AQSTR + 64*AQSTR + 128*AVSTR + 8*16*APSTR) * 2) // 89088 B

__global__ __launch_bounds__(256) void attn_mma_kernel()
{
    extern __shared__ __align__(16) __half sm[];
    __half* Qs = sm;                           // 128*136 = 17408 h
    __half* Ks = sm + 128 * AQSTR;             // 64*136  = 8704 h
    __half* Vs = Ks + 64 * AQSTR;              // 128*72  = 9216 h
    __half* Ps = Vs + 128 * AVSTR;             // 8*16*72 = 9216 h

    const int t     = threadIdx.x;
    const int w     = t >> 5;
    const int lane  = t & 31;
    const int r     = lane >> 2;
    const int c     = lane & 3;
    const int qtile = (int)gridDim.x - 1 - (int)blockIdx.x;   // heavy tiles first
    const int h     = blockIdx.y;
    const int b     = blockIdx.z;
    const int q0    = qtile * QT_;
    const int kvh   = h >> 2;

    __half* Psw = Ps + w * (16 * APSTR);

    // ---- load Q tile ----
    {
        const uint4* Qg4 = (const uint4*)(g_Q + ((size_t)(b * S_ + q0) * NH_ + h) * HD_);
        #pragma unroll
        for (int i = 0; i < 8; i++) {
            int lin = t + i * 256;
            int row = lin >> 4, ch = lin & 15;
            *(uint4*)&Qs[row * AQSTR + ch * 8] = Qg4[row * (NH_ * HD_ / 8) + ch];
        }
    }

    float m0 = MINIT_, m1 = MINIT_, l0 = 0.f, l1 = 0.f;
    float acc[16][4];
    #pragma unroll
    for (int nt = 0; nt < 16; nt++)
        #pragma unroll
        for (int x = 0; x < 4; x++) acc[nt][x] = 0.f;

    const int gi0 = q0 + w * 16 + r;
    const int gi1 = gi0 + 8;
    const int kb_lo = (q0 >= WIN_) ? ((q0 - WIN_) >> 6) : 0;
    const int kb_hi = (q0 + QT_ - 1) >> 6;
    const float scale = 0.08838834764831845f;   // 1/sqrt(128)

    for (int kb = kb_lo; kb <= kb_hi; kb++) {
        __syncthreads();
        // ---- load K (64x128) and V^T (128 hd x 64 keys) ----
        {
            const uint4* Kg4 = (const uint4*)(g_K +
                ((size_t)(b * S_ + kb * 64) * NKV_ + kvh) * HD_);
            const uint4* Vg4 = (const uint4*)(g_Vt +
                ((size_t)(b * NKV_ + kvh) * HD_) * S_ + kb * 64);
            #pragma unroll
            for (int i = 0; i < 4; i++) {
                int lin = t + i * 256;
                int row = lin >> 4, ch = lin & 15;
                *(uint4*)&Ks[row * AQSTR + ch * 8] = Kg4[row * (NKV_ * HD_ / 8) + ch];
                int vrow = lin >> 3, vch = lin & 7;
                *(uint4*)&Vs[vrow * AVSTR + vch * 8] = Vg4[vrow * (S_ / 8) + vch];
            }
        }
        __syncthreads();

        // ---- S = Q @ K^T : per warp 16x64, 8 k-steps of 16 ----
        float s[8][4];
        #pragma unroll
        for (int nt = 0; nt < 8; nt++)
            #pragma unroll
            for (int x = 0; x < 4; x++) s[nt][x] = 0.f;

        #pragma unroll
        for (int ks = 0; ks < 8; ks++) {
            const __half* qp = Qs + (w * 16 + r) * AQSTR + ks * 16 + 2 * c;
            unsigned a0 = ldu32(qp);
            unsigned a1 = ldu32(qp + 8 * AQSTR);
            unsigned a2 = ldu32(qp + 8);
            unsigned a3 = ldu32(qp + 8 * AQSTR + 8);
            #pragma unroll
            for (int nt = 0; nt < 8; nt++) {
                const __half* kp = Ks + (nt * 8 + r) * AQSTR + ks * 16 + 2 * c;
                mma_f16(s[nt], a0, a1, a2, a3, ldu32(kp), ldu32(kp + 8));
            }
        }

        // ---- scale + window mask + row max ----
        float mx0 = MASKED_, mx1 = MASKED_;
        #pragma unroll
        for (int nt = 0; nt < 8; nt++) {
            #pragma unroll
            for (int jj = 0; jj < 2; jj++) {
                int gj = kb * 64 + nt * 8 + 2 * c + jj;
                float v0 = s[nt][jj] * scale;
                v0 = (gj <= gi0 && gj + WIN_ >= gi0) ? v0 : MASKED_;
                s[nt][jj] = v0;
                mx0 = fmaxf(mx0, v0);
                float v1 = s[nt][2 + jj] * scale;
                v1 = (gj <= gi1 && gj + WIN_ >= gi1) ? v1 : MASKED_;
                s[nt][2 + jj] = v1;
                mx1 = fmaxf(mx1, v1);
            }
        }
        mx0 = fmaxf(mx0, __shfl_xor_sync(0xffffffffu, mx0, 1));
        mx0 = fmaxf(mx0, __shfl_xor_sync(0xffffffffu, mx0, 2));
        mx1 = fmaxf(mx1, __shfl_xor_sync(0xffffffffu, mx1, 1));
        mx1 = fmaxf(mx1, __shfl_xor_sync(0xffffffffu, mx1, 2));

        const float mn0 = fmaxf(m0, mx0);
        const float mn1 = fmaxf(m1, mx1);
        const float al0 = __expf(m0 - mn0);
        const float al1 = __expf(m1 - mn1);
        m0 = mn0; m1 = mn1;
        l0 *= al0; l1 *= al1;
        #pragma unroll
        for (int nt = 0; nt < 16; nt++) {
            acc[nt][0] *= al0; acc[nt][1] *= al0;
            acc[nt][2] *= al1; acc[nt][3] *= al1;
        }

        // ---- exp + fp16 P to per-warp smem ----
        float ss0 = 0.f, ss1 = 0.f;
        #pragma unroll
        for (int nt = 0; nt < 8; nt++) {
            __half2 h01 = __floats2half2_rn(__expf(s[nt][0] - mn0),
                                            __expf(s[nt][1] - mn0));
            __half2 h23 = __floats2half2_rn(__expf(s[nt][2] - mn1),
                                            __expf(s[nt][3] - mn1));
            ss0 += __low2float(h01) + __high2float(h01);
            ss1 += __low2float(h23) + __high2float(h23);
            *(__half2*)&Psw[r * APSTR + nt * 8 + 2 * c]       = h01;
            *(__half2*)&Psw[(r + 8) * APSTR + nt * 8 + 2 * c] = h23;
        }
        ss0 += __shfl_xor_sync(0xffffffffu, ss0, 1);
        ss0 += __shfl_xor_sync(0xffffffffu, ss0, 2);
        ss1 += __shfl_xor_sync(0xffffffffu, ss1, 1);
        ss1 += __shfl_xor_sync(0xffffffffu, ss1, 2);
        l0 += ss0; l1 += ss1;

        __syncwarp();

        // ---- O += P @ V : 16 n-tiles x 4 k-steps of 16 ----
        #pragma unroll
        for (int ks = 0; ks < 4; ks++) {
            const __half* pp = Psw + r * APSTR + ks * 16 + 2 * c;
            unsigned a0 = ldu32(pp);
            unsigned a1 = ldu32(pp + 8 * APSTR);
            unsigned a2 = ldu32(pp + 8);
            unsigned a3 = ldu32(pp + 8 * APSTR + 8);
            #pragma unroll
            for (int nt = 0; nt < 16; nt++) {
                const __half* vp = Vs + (nt * 8 + r) * AVSTR + ks * 16 + 2 * c;
                mma_f16(acc[nt], a0, a1, a2, a3, ldu32(vp), ldu32(vp + 8));
            }
        }
    }

    // ---- epilogue: normalized fp16 AO ----
    const float il0 = 1.f / l0;
    const float il1 = 1.f / l1;
    __half* O0 = g_AO + ((size_t)(b * S_ + gi0) * NH_ + h) * HD_;
    __half* O1 = g_AO + ((size_t)(b * S_ + gi1) * NH_ + h) * HD_;
    #pragma unroll
    for (int nt = 0; nt < 16; nt++) {
        int col = nt * 8 + 2 * c;
        *(__half2*)(O0 + col) = __floats2half2_rn(acc[nt][0] * il0, acc[nt][1] * il0);
        *(__half2*)(O1 + col) = __floats2half2_rn(acc[nt][2] * il1, acc[nt][3] * il1);
    }
}

// ===========================================================================
extern "C" void kernel_launch(void* const* d_in, const int* in_sizes, int n_in,
                              void* d_out, int out_size)
{
    (void)in_sizes; (void)n_in; (void)out_size;
    const float* hidden  = (const float*)d_in[0];
    const int*   pos_ids = (const int*)d_in[2];
    const float* q_w     = (const float*)d_in[3];
    const float* k_w     = (const float*)d_in[4];
    const float* v_w     = (const float*)d_in[5];
    const float* o_w     = (const float*)d_in[6];
    float* out = (float*)d_out;

    __half *Hh, *Wq, *Wk, *Wv, *Wo, *Qh, *Kh, *Vh, *AOh;
    cudaGetSymbolAddress((void**)&Hh,  g_Hh);
    cudaGetSymbolAddress((void**)&Wq,  g_Wq);
    cudaGetSymbolAddress((void**)&Wk,  g_Wk);
    cudaGetSymbolAddress((void**)&Wv,  g_Wv);
    cudaGetSymbolAddress((void**)&Wo,  g_Wo);
    cudaGetSymbolAddress((void**)&Qh,  g_Q);
    cudaGetSymbolAddress((void**)&Kh,  g_K);
    cudaGetSymbolAddress((void**)&Vh,  g_V);
    cudaGetSymbolAddress((void**)&AOh, g_AO);

    cudaFuncSetAttribute(h16_gemm<__half>,
        cudaFuncAttributeMaxDynamicSharedMemorySize, HGEMM_SMEM);
    cudaFuncSetAttribute(h16_gemm<float>,
        cudaFuncAttributeMaxDynamicSharedMemorySize, HGEMM_SMEM);
    cudaFuncSetAttribute(attn_mma_kernel,
        cudaFuncAttributeMaxDynamicSharedMemorySize, ATTN_SMEM);

    // Prep: fp16 conversions + weight transposes
    cvt_h<<<(MROWS * HID_ / 4) / 256, 256>>>(hidden, Hh);
    transpose_h<<<dim3(HID_ / 32, HID_ / 32), dim3(32, 8)>>>(q_w, Wq, HID_, HID_);
    transpose_h<<<dim3((NKV_ * HD_) / 32, HID_ / 32), dim3(32, 8)>>>(k_w, Wk, HID_, NKV_ * HD_);
    transpose_h<<<dim3((NKV_ * HD_) / 32, HID_ / 32), dim3(32, 8)>>>(v_w, Wv, HID_, NKV_ * HD_);
    transpose_h<<<dim3(HID_ / 32, HID_ / 32), dim3(32, 8)>>>(o_w, Wo, HID_, HID_);

    // QKV projections (fp16 in/out, fp32 accum)
    h16_gemm<__half><<<dim3(NH_ * HD_ / 128, MROWS / 128), 256, HGEMM_SMEM>>>(
        Hh, Wq, Qh, MROWS, NH_ * HD_, HID_);
    h16_gemm<__half><<<dim3(NKV_ * HD_ / 128, MROWS / 128), 256, HGEMM_SMEM>>>(
        Hh, Wk, Kh, MROWS, NKV_ * HD_, HID_);
    h16_gemm<__half><<<dim3(NKV_ * HD_ / 128, MROWS / 128), 256, HGEMM_SMEM>>>(
        Hh, Wv, Vh, MROWS, NKV_ * HD_, HID_);

    // RoPE (fp16 in-place) + V transpose
    {
        int total = MROWS * NH_ * 32 + MROWS * NKV_ * 32;
        rope_h<<<(total + 255) / 256, 256>>>(pos_ids);
    }
    vtrans_h<<<dim3(S_ / 32, HD_ / 32, B_ * NKV_), dim3(32, 8)>>>();

    // Attention
    attn_mma_kernel<<<dim3(S_ / QT_, NH_, B_), 256, ATTN_SMEM>>>();

    // Output projection (fp16 A/B, fp32 out)
    h16_gemm<float><<<dim3(HID_ / 128, MROWS / 128), 256, HGEMM_SMEM>>>(
        AOh, Wo, out, MROWS, HID_, HID_);
}

// round 15
// speedup vs baseline: 1.0003x; 1.0003x over previous
#include <cuda_runtime.h>
#include <cuda_fp16.h>
#include <cstdint>

#define B_    2
#define S_    2048
#define HID_  4096
#define NH_   32
#define NKV_  8
#define HD_   128
#define MROWS (B_ * S_)     // 4096
#define WIN_  1024

// Scratch (allocation-free: __device__ globals), fp16 — ~200 MB total
__device__ __half g_Hh[(size_t)MROWS * HID_];        // 32 MB hidden fp16
__device__ __half g_Wq[(size_t)HID_ * HID_];         // 32 MB [N][K]
__device__ __half g_Wk[(size_t)(NKV_ * HD_) * HID_]; // 8 MB
__device__ __half g_Wv[(size_t)(NKV_ * HD_) * HID_]; // 8 MB
__device__ __half g_Wo[(size_t)HID_ * HID_];         // 32 MB
__device__ __half g_Q [(size_t)MROWS * NH_ * HD_];   // 32 MB
__device__ __half g_K [(size_t)MROWS * NKV_ * HD_];  // 8 MB
__device__ __half g_V [(size_t)MROWS * NKV_ * HD_];  // 8 MB
__device__ __half g_Vt[(size_t)B_ * NKV_ * HD_ * S_];// 8 MB  [b][kvh][hd][s]
__device__ __half g_AO[(size_t)MROWS * NH_ * HD_];   // 32 MB

__device__ __forceinline__ void mma_f16(
    float* c, unsigned a0, unsigned a1, unsigned a2, unsigned a3,
    unsigned b0, unsigned b1)
{
    asm volatile(
        "mma.sync.aligned.m16n8k16.row.col.f32.f16.f16.f32 "
        "{%0,%1,%2,%3}, {%4,%5,%6,%7}, {%8,%9}, {%0,%1,%2,%3};\n"
        : "+f"(c[0]), "+f"(c[1]), "+f"(c[2]), "+f"(c[3])
        : "r"(a0), "r"(a1), "r"(a2), "r"(a3), "r"(b0), "r"(b1));
}

__device__ __forceinline__ unsigned ldu32(const __half* p) {
    return *reinterpret_cast<const unsigned*>(p);
}

// epilogue pair-store: fp32 or fp16 C
__device__ __forceinline__ void stpair(float* C, size_t idx, float a, float b) {
    *(float2*)(C + idx) = make_float2(a, b);
}
__device__ __forceinline__ void stpair(__half* C, size_t idx, float a, float b) {
    *(__half2*)(C + idx) = __floats2half2_rn(a, b);
}

// ===========================================================================
// FP16 tensor-core GEMM: C[M,N] = A[M,K] @ Bt[N,K]^T   (both fp16, K-contig)
// 128x128 tile, BK=64, 256 threads (8 warps), warp tile 64x32, m16n8k16.
// Smem rows stride 72 halfs -> fragment LDS bank == lane (conflict-free).
// ===========================================================================
#define HSTR 72
#define HSZ  (128 * HSTR)          // 9216 halfs per tile
#define HGEMM_SMEM (4 * HSZ * 2)   // 73728 B (A x2, B x2)

template <typename CT>
__global__ __launch_bounds__(256) void h16_gemm(
    const __half* __restrict__ A, const __half* __restrict__ Bt,
    CT* __restrict__ C, int M, int N, int K)
{
    extern __shared__ __align__(16) __half sh[];
    __half* As = sh;              // 2 x HSZ
    __half* Bs = sh + 2 * HSZ;    // 2 x HSZ

    const int t    = threadIdx.x;
    const int warp = t >> 5;
    const int lane = t & 31;
    const int r    = lane >> 2;
    const int c    = lane & 3;
    const int wm   = (warp >> 2) * 64;
    const int wn   = (warp & 3) * 32;
    const int bm   = blockIdx.y * 128;
    const int bn   = blockIdx.x * 128;

    // loader mapping: 128 rows x 8 uint4-chunks (64 halfs/row), 4 iters
    const uint4* agp[4];
    const uint4* bgp[4];
    int soff[4];
    #pragma unroll
    for (int i = 0; i < 4; i++) {
        int lin = t + i * 256;
        int row = lin >> 3, ch = lin & 7;
        agp[i] = (const uint4*)(A  + (size_t)(bm + row) * K) + ch;
        bgp[i] = (const uint4*)(Bt + (size_t)(bn + row) * K) + ch;
        soff[i] = row * HSTR + ch * 8;
    }

    const int NKT = K / 64;
    uint4 ra[4], rb[4];

    #pragma unroll
    for (int i = 0; i < 4; i++) { ra[i] = agp[i][0]; rb[i] = bgp[i][0]; }
    #pragma unroll
    for (int i = 0; i < 4; i++) {
        *(uint4*)&As[soff[i]] = ra[i];
        *(uint4*)&Bs[soff[i]] = rb[i];
    }
    __syncthreads();

    float acc[4][4][4];
    #pragma unroll
    for (int mt = 0; mt < 4; mt++)
        #pragma unroll
        for (int nt = 0; nt < 4; nt++)
            #pragma unroll
            for (int x = 0; x < 4; x++) acc[mt][nt][x] = 0.f;

    for (int kt = 0; kt < NKT; kt++) {
        if (kt + 1 < NKT) {
            #pragma unroll
            for (int i = 0; i < 4; i++) {
                ra[i] = agp[i][(kt + 1) * 8];
                rb[i] = bgp[i][(kt + 1) * 8];
            }
        }

        const __half* Ab = As + (kt & 1) * HSZ;
        const __half* Bb = Bs + (kt & 1) * HSZ;

        #pragma unroll
        for (int ks = 0; ks < 4; ks++) {
            unsigned af[4][4], bf[4][2];
            #pragma unroll
            for (int mt = 0; mt < 4; mt++) {
                const __half* p = Ab + (wm + mt * 16 + r) * HSTR + ks * 16 + 2 * c;
                af[mt][0] = ldu32(p);
                af[mt][1] = ldu32(p + 8 * HSTR);
                af[mt][2] = ldu32(p + 8);
                af[mt][3] = ldu32(p + 8 * HSTR + 8);
            }
            #pragma unroll
            for (int nt = 0; nt < 4; nt++) {
                const __half* p = Bb + (wn + nt * 8 + r) * HSTR + ks * 16 + 2 * c;
                bf[nt][0] = ldu32(p);
                bf[nt][1] = ldu32(p + 8);
            }
            #pragma unroll
            for (int mt = 0; mt < 4; mt++)
                #pragma unroll
                for (int nt = 0; nt < 4; nt++)
                    mma_f16(acc[mt][nt], af[mt][0], af[mt][1], af[mt][2], af[mt][3],
                            bf[nt][0], bf[nt][1]);
        }

        if (kt + 1 < NKT) {
            __half* Abn = As + ((kt + 1) & 1) * HSZ;
            __half* Bbn = Bs + ((kt + 1) & 1) * HSZ;
            #pragma unroll
            for (int i = 0; i < 4; i++) {
                *(uint4*)&Abn[soff[i]] = ra[i];
                *(uint4*)&Bbn[soff[i]] = rb[i];
            }
        }
        __syncthreads();
    }

    #pragma unroll
    for (int mt = 0; mt < 4; mt++) {
        const int row0 = bm + wm + mt * 16 + r;
        #pragma unroll
        for (int nt = 0; nt < 4; nt++) {
            const int col = bn + wn + nt * 8 + 2 * c;
            stpair(C, (size_t)row0 * N + col,       acc[mt][nt][0], acc[mt][nt][1]);
            stpair(C, (size_t)(row0 + 8) * N + col, acc[mt][nt][2], acc[mt][nt][3]);
        }
    }
}

// ===========================================================================
// Prep kernels
// ===========================================================================
__global__ void cvt_h(const float* __restrict__ src, __half* __restrict__ dst)
{
    size_t i = (size_t)blockIdx.x * blockDim.x + threadIdx.x;
    float4 v = *(const float4*)(src + i * 4);
    __half2 h0 = __floats2half2_rn(v.x, v.y);
    __half2 h1 = __floats2half2_rn(v.z, v.w);
    uint2 o;
    o.x = *reinterpret_cast<unsigned*>(&h0);
    o.y = *reinterpret_cast<unsigned*>(&h1);
    *(uint2*)(dst + i * 4) = o;
}

// src [K][N] fp32 -> dst [N][K] fp16
__global__ void transpose_h(const float* __restrict__ src, __half* __restrict__ dst,
                            int K, int N)
{
    __shared__ float tile[32][33];
    int x = blockIdx.x * 32 + threadIdx.x;   // n
    int y = blockIdx.y * 32 + threadIdx.y;   // k
    #pragma unroll
    for (int i = 0; i < 32; i += 8)
        tile[threadIdx.y + i][threadIdx.x] = src[(size_t)(y + i) * N + x];
    __syncthreads();
    int x2 = blockIdx.y * 32 + threadIdx.x;  // k
    int y2 = blockIdx.x * 32 + threadIdx.y;  // n
    #pragma unroll
    for (int i = 0; i < 32; i += 8)
        dst[(size_t)(y2 + i) * K + x2] = __float2half_rn(tile[threadIdx.x][threadIdx.y + i]);
}

// g_V [m][kvh*HD+hd] -> g_Vt [b][kvh][hd][s]
__global__ void vtrans_h()
{
    __shared__ __half tile[32][33];
    int b   = blockIdx.z >> 3;
    int kvh = blockIdx.z & 7;
    int x = blockIdx.y * 32 + threadIdx.x;   // hd
    int y = blockIdx.x * 32 + threadIdx.y;   // s
    #pragma unroll
    for (int i = 0; i < 32; i += 8)
        tile[threadIdx.y + i][threadIdx.x] =
            g_V[(size_t)(b * S_ + y + i) * (NKV_ * HD_) + kvh * HD_ + x];
    __syncthreads();
    int x2 = blockIdx.x * 32 + threadIdx.x;  // s
    int y2 = blockIdx.y * 32 + threadIdx.y;  // hd
    #pragma unroll
    for (int i = 0; i < 32; i += 8)
        g_Vt[((size_t)(b * NKV_ + kvh) * HD_ + y2 + i) * S_ + x2] =
            tile[threadIdx.x][threadIdx.y + i];
}

// RoPE in-place on fp16 g_Q, g_K. One thread per half2 pair (2p,2p+1 | +64).
__global__ void rope_h(const int* __restrict__ pos_ids)
{
    const int QP = MROWS * NH_ * 32;    // 4194304
    const int KP = MROWS * NKV_ * 32;   // 1048576
    int idx = blockIdx.x * blockDim.x + threadIdx.x;
    if (idx >= QP + KP) return;

    __half* base;
    int m, p;
    if (idx < QP) {
        m = idx >> 10;
        int rem = idx & 1023;
        base = g_Q + ((size_t)m * NH_ + (rem >> 5)) * HD_;
        p = rem & 31;
    } else {
        int i2 = idx - QP;
        m = i2 >> 8;
        int rem = i2 & 255;
        base = g_K + ((size_t)m * NKV_ + (rem >> 5)) * HD_;
        p = rem & 31;
    }
    float pos = (float)pos_ids[m];
    float i0 = exp2f((float)(2 * p)     * -0.20762050593045857f);
    float i1 = exp2f((float)(2 * p + 1) * -0.20762050593045857f);
    float s0, c0, s1, c1;
    sincosf(pos * i0, &s0, &c0);
    sincosf(pos * i1, &s1, &c1);

    __half2 lo = *(__half2*)(base + 2 * p);
    __half2 hi = *(__half2*)(base + 64 + 2 * p);
    float x00 = __low2float(lo),  x01 = __high2float(lo);
    float x10 = __low2float(hi),  x11 = __high2float(hi);
    *(__half2*)(base + 2 * p)      = __floats2half2_rn(x00 * c0 - x10 * s0,
                                                       x01 * c1 - x11 * s1);
    *(__half2*)(base + 64 + 2 * p) = __floats2half2_rn(x10 * c0 + x00 * s0,
                                                       x11 * c1 + x01 * s1);
}

// ===========================================================================
// FP16 tensor-core flash attention, sliding window 1024, GQA.
// Block = (q_tile 128, head, batch), 256 threads (8 warps x 16 q-rows).
// Qs/Ks [row][136h], Vs [hd][72h], Ps per-warp [16][72h] — all frag LDS
// bank-conflict-free (bank == 4r+c == lane).
// ===========================================================================
#define AQSTR 136
#define AVSTR 72
#define APSTR 72
#define QT_ 128
#define MASKED_ (-30000.0f)
#define MINIT_  (-10000.0f)
#define ATTN_SMEM ((128*AQSTR + 64*AQSTR + 128*AVSTR + 8*16*APSTR) * 2) // 89088 B

__global__ __launch_bounds__(256) void attn_mma_kernel()
{
    extern __shared__ __align__(16) __half sm[];
    __half* Qs = sm;                           // 128*136 = 17408 h
    __half* Ks = sm + 128 * AQSTR;             // 64*136  = 8704 h
    __half* Vs = Ks + 64 * AQSTR;              // 128*72  = 9216 h
    __half* Ps = Vs + 128 * AVSTR;             // 8*16*72 = 9216 h

    const int t     = threadIdx.x;
    const int w     = t >> 5;
    const int lane  = t & 31;
    const int r     = lane >> 2;
    const int c     = lane & 3;
    const int qtile = (int)gridDim.x - 1 - (int)blockIdx.x;   // heavy tiles first
    const int h     = blockIdx.y;
    const int b     = blockIdx.z;
    const int q0    = qtile * QT_;
    const int kvh   = h >> 2;

    __half* Psw = Ps + w * (16 * APSTR);

    // ---- load Q tile ----
    {
        const uint4* Qg4 = (const uint4*)(g_Q + ((size_t)(b * S_ + q0) * NH_ + h) * HD_);
        #pragma unroll
        for (int i = 0; i < 8; i++) {
            int lin = t + i * 256;
            int row = lin >> 4, ch = lin & 15;
            *(uint4*)&Qs[row * AQSTR + ch * 8] = Qg4[row * (NH_ * HD_ / 8) + ch];
        }
    }

    float m0 = MINIT_, m1 = MINIT_, l0 = 0.f, l1 = 0.f;
    float acc[16][4];
    #pragma unroll
    for (int nt = 0; nt < 16; nt++)
        #pragma unroll
        for (int x = 0; x < 4; x++) acc[nt][x] = 0.f;

    const int gi0 = q0 + w * 16 + r;
    const int gi1 = gi0 + 8;
    const int kb_lo = (q0 >= WIN_) ? ((q0 - WIN_) >> 6) : 0;
    const int kb_hi = (q0 + QT_ - 1) >> 6;
    const float scale = 0.08838834764831845f;   // 1/sqrt(128)

    for (int kb = kb_lo; kb <= kb_hi; kb++) {
        __syncthreads();
        // ---- load K (64x128) and V^T (128 hd x 64 keys) ----
        {
            const uint4* Kg4 = (const uint4*)(g_K +
                ((size_t)(b * S_ + kb * 64) * NKV_ + kvh) * HD_);
            const uint4* Vg4 = (const uint4*)(g_Vt +
                ((size_t)(b * NKV_ + kvh) * HD_) * S_ + kb * 64);
            #pragma unroll
            for (int i = 0; i < 4; i++) {
                int lin = t + i * 256;
                int row = lin >> 4, ch = lin & 15;
                *(uint4*)&Ks[row * AQSTR + ch * 8] = Kg4[row * (NKV_ * HD_ / 8) + ch];
                int vrow = lin >> 3, vch = lin & 7;
                *(uint4*)&Vs[vrow * AVSTR + vch * 8] = Vg4[vrow * (S_ / 8) + vch];
            }
        }
        __syncthreads();

        // ---- S = Q @ K^T : per warp 16x64, 8 k-steps of 16 ----
        float s[8][4];
        #pragma unroll
        for (int nt = 0; nt < 8; nt++)
            #pragma unroll
            for (int x = 0; x < 4; x++) s[nt][x] = 0.f;

        #pragma unroll
        for (int ks = 0; ks < 8; ks++) {
            const __half* qp = Qs + (w * 16 + r) * AQSTR + ks * 16 + 2 * c;
            unsigned a0 = ldu32(qp);
            unsigned a1 = ldu32(qp + 8 * AQSTR);
            unsigned a2 = ldu32(qp + 8);
            unsigned a3 = ldu32(qp + 8 * AQSTR + 8);
            #pragma unroll
            for (int nt = 0; nt < 8; nt++) {
                const __half* kp = Ks + (nt * 8 + r) * AQSTR + ks * 16 + 2 * c;
                mma_f16(s[nt], a0, a1, a2, a3, ldu32(kp), ldu32(kp + 8));
            }
        }

        // ---- scale + window mask + row max ----
        float mx0 = MASKED_, mx1 = MASKED_;
        #pragma unroll
        for (int nt = 0; nt < 8; nt++) {
            #pragma unroll
            for (int jj = 0; jj < 2; jj++) {
                int gj = kb * 64 + nt * 8 + 2 * c + jj;
                float v0 = s[nt][jj] * scale;
                v0 = (gj <= gi0 && gj + WIN_ >= gi0) ? v0 : MASKED_;
                s[nt][jj] = v0;
                mx0 = fmaxf(mx0, v0);
                float v1 = s[nt][2 + jj] * scale;
                v1 = (gj <= gi1 && gj + WIN_ >= gi1) ? v1 : MASKED_;
                s[nt][2 + jj] = v1;
                mx1 = fmaxf(mx1, v1);
            }
        }
        mx0 = fmaxf(mx0, __shfl_xor_sync(0xffffffffu, mx0, 1));
        mx0 = fmaxf(mx0, __shfl_xor_sync(0xffffffffu, mx0, 2));
        mx1 = fmaxf(mx1, __shfl_xor_sync(0xffffffffu, mx1, 1));
        mx1 = fmaxf(mx1, __shfl_xor_sync(0xffffffffu, mx1, 2));

        const float mn0 = fmaxf(m0, mx0);
        const float mn1 = fmaxf(m1, mx1);
        const float al0 = __expf(m0 - mn0);
        const float al1 = __expf(m1 - mn1);
        m0 = mn0; m1 = mn1;
        l0 *= al0; l1 *= al1;
        #pragma unroll
        for (int nt = 0; nt < 16; nt++) {
            acc[nt][0] *= al0; acc[nt][1] *= al0;
            acc[nt][2] *= al1; acc[nt][3] *= al1;
        }

        // ---- exp + fp16 P to per-warp smem ----
        float ss0 = 0.f, ss1 = 0.f;
        #pragma unroll
        for (int nt = 0; nt < 8; nt++) {
            __half2 h01 = __floats2half2_rn(__expf(s[nt][0] - mn0),
                                            __expf(s[nt][1] - mn0));
            __half2 h23 = __floats2half2_rn(__expf(s[nt][2] - mn1),
                                            __expf(s[nt][3] - mn1));
            ss0 += __low2float(h01) + __high2float(h01);
            ss1 += __low2float(h23) + __high2float(h23);
            *(__half2*)&Psw[r * APSTR + nt * 8 + 2 * c]       = h01;
            *(__half2*)&Psw[(r + 8) * APSTR + nt * 8 + 2 * c] = h23;
        }
        ss0 += __shfl_xor_sync(0xffffffffu, ss0, 1);
        ss0 += __shfl_xor_sync(0xffffffffu, ss0, 2);
        ss1 += __shfl_xor_sync(0xffffffffu, ss1, 1);
        ss1 += __shfl_xor_sync(0xffffffffu, ss1, 2);
        l0 += ss0; l1 += ss1;

        __syncwarp();

        // ---- O += P @ V : 16 n-tiles x 4 k-steps of 16 ----
        #pragma unroll
        for (int ks = 0; ks < 4; ks++) {
            const __half* pp = Psw + r * APSTR + ks * 16 + 2 * c;
            unsigned a0 = ldu32(pp);
            unsigned a1 = ldu32(pp + 8 * APSTR);
            unsigned a2 = ldu32(pp + 8);
            unsigned a3 = ldu32(pp + 8 * APSTR + 8);
            #pragma unroll
            for (int nt = 0; nt < 16; nt++) {
                const __half* vp = Vs + (nt * 8 + r) * AVSTR + ks * 16 + 2 * c;
                mma_f16(acc[nt], a0, a1, a2, a3, ldu32(vp), ldu32(vp + 8));
            }
        }
    }

    // ---- epilogue: normalized fp16 AO ----
    const float il0 = 1.f / l0;
    const float il1 = 1.f / l1;
    __half* O0 = g_AO + ((size_t)(b * S_ + gi0) * NH_ + h) * HD_;
    __half* O1 = g_AO + ((size_t)(b * S_ + gi1) * NH_ + h) * HD_;
    #pragma unroll
    for (int nt = 0; nt < 16; nt++) {
        int col = nt * 8 + 2 * c;
        *(__half2*)(O0 + col) = __floats2half2_rn(acc[nt][0] * il0, acc[nt][1] * il0);
        *(__half2*)(O1 + col) = __floats2half2_rn(acc[nt][2] * il1, acc[nt][3] * il1);
    }
}

// ===========================================================================
extern "C" void kernel_launch(void* const* d_in, const int* in_sizes, int n_in,
                              void* d_out, int out_size)
{
    (void)in_sizes; (void)n_in; (void)out_size;
    const float* hidden  = (const float*)d_in[0];
    const int*   pos_ids = (const int*)d_in[2];
    const float* q_w     = (const float*)d_in[3];
    const float* k_w     = (const float*)d_in[4];
    const float* v_w     = (const float*)d_in[5];
    const float* o_w     = (const float*)d_in[6];
    float* out = (float*)d_out;

    __half *Hh, *Wq, *Wk, *Wv, *Wo, *Qh, *Kh, *Vh, *AOh;
    cudaGetSymbolAddress((void**)&Hh,  g_Hh);
    cudaGetSymbolAddress((void**)&Wq,  g_Wq);
    cudaGetSymbolAddress((void**)&Wk,  g_Wk);
    cudaGetSymbolAddress((void**)&Wv,  g_Wv);
    cudaGetSymbolAddress((void**)&Wo,  g_Wo);
    cudaGetSymbolAddress((void**)&Qh,  g_Q);
    cudaGetSymbolAddress((void**)&Kh,  g_K);
    cudaGetSymbolAddress((void**)&Vh,  g_V);
    cudaGetSymbolAddress((void**)&AOh, g_AO);

    cudaFuncSetAttribute(h16_gemm<__half>,
        cudaFuncAttributeMaxDynamicSharedMemorySize, HGEMM_SMEM);
    cudaFuncSetAttribute(h16_gemm<float>,
        cudaFuncAttributeMaxDynamicSharedMemorySize, HGEMM_SMEM);
    cudaFuncSetAttribute(attn_mma_kernel,
        cudaFuncAttributeMaxDynamicSharedMemorySize, ATTN_SMEM);

    // Prep: fp16 conversions + weight transposes
    cvt_h<<<(MROWS * HID_ / 4) / 256, 256>>>(hidden, Hh);
    transpose_h<<<dim3(HID_ / 32, HID_ / 32), dim3(32, 8)>>>(q_w, Wq, HID_, HID_);
    transpose_h<<<dim3((NKV_ * HD_) / 32, HID_ / 32), dim3(32, 8)>>>(k_w, Wk, HID_, NKV_ * HD_);
    transpose_h<<<dim3((NKV_ * HD_) / 32, HID_ / 32), dim3(32, 8)>>>(v_w, Wv, HID_, NKV_ * HD_);
    transpose_h<<<dim3(HID_ / 32, HID_ / 32), dim3(32, 8)>>>(o_w, Wo, HID_, HID_);

    // QKV projections (fp16 in/out, fp32 accum)
    h16_gemm<__half><<<dim3(NH_ * HD_ / 128, MROWS / 128), 256, HGEMM_SMEM>>>(
        Hh, Wq, Qh, MROWS, NH_ * HD_, HID_);
    h16_gemm<__half><<<dim3(NKV_ * HD_ / 128, MROWS / 128), 256, HGEMM_SMEM>>>(
        Hh, Wk, Kh, MROWS, NKV_ * HD_, HID_);
    h16_gemm<__half><<<dim3(NKV_ * HD_ / 128, MROWS / 128), 256, HGEMM_SMEM>>>(
        Hh, Wv, Vh, MROWS, NKV_ * HD_, HID_);

    // RoPE (fp16 in-place) + V transpose
    {
        int total = MROWS * NH_ * 32 + MROWS * NKV_ * 32;
        rope_h<<<(total + 255) / 256, 256>>>(pos_ids);
    }
    vtrans_h<<<dim3(S_ / 32, HD_ / 32, B_ * NKV_), dim3(32, 8)>>>();

    // Attention
    attn_mma_kernel<<<dim3(S_ / QT_, NH_, B_), 256, ATTN_SMEM>>>();

    // Output projection (fp16 A/B, fp32 out)
    h16_gemm<float><<<dim3(HID_ / 128, MROWS / 128), 256, HGEMM_SMEM>>>(
        AOh, Wo, out, MROWS, HID_, HID_);
}

// round 16
// speedup vs baseline: 1.0010x; 1.0007x over previous
#include <cuda_runtime.h>
#include <cuda_fp16.h>
#include <cstdint>

#define B_    2
#define S_    2048
#define HID_  4096
#define NH_   32
#define NKV_  8
#define HD_   128
#define MROWS (B_ * S_)     // 4096
#define WIN_  1024

// Scratch (allocation-free: __device__ globals), fp16 — ~200 MB total
__device__ __half g_Hh[(size_t)MROWS * HID_];        // 32 MB hidden fp16
__device__ __half g_Wq[(size_t)HID_ * HID_];         // 32 MB [N][K]
__device__ __half g_Wk[(size_t)(NKV_ * HD_) * HID_]; // 8 MB
__device__ __half g_Wv[(size_t)(NKV_ * HD_) * HID_]; // 8 MB
__device__ __half g_Wo[(size_t)HID_ * HID_];         // 32 MB
__device__ __half g_Q [(size_t)MROWS * NH_ * HD_];   // 32 MB
__device__ __half g_K [(size_t)MROWS * NKV_ * HD_];  // 8 MB
__device__ __half g_V [(size_t)MROWS * NKV_ * HD_];  // 8 MB
__device__ __half g_Vt[(size_t)B_ * NKV_ * HD_ * S_];// 8 MB  [b][kvh][hd][s]
__device__ __half g_AO[(size_t)MROWS * NH_ * HD_];   // 32 MB

__device__ __forceinline__ void mma_f16(
    float* c, unsigned a0, unsigned a1, unsigned a2, unsigned a3,
    unsigned b0, unsigned b1)
{
    asm volatile(
        "mma.sync.aligned.m16n8k16.row.col.f32.f16.f16.f32 "
        "{%0,%1,%2,%3}, {%4,%5,%6,%7}, {%8,%9}, {%0,%1,%2,%3};\n"
        : "+f"(c[0]), "+f"(c[1]), "+f"(c[2]), "+f"(c[3])
        : "r"(a0), "r"(a1), "r"(a2), "r"(a3), "r"(b0), "r"(b1));
}

__device__ __forceinline__ unsigned ldu32(const __half* p) {
    return *reinterpret_cast<const unsigned*>(p);
}

// epilogue pair-store: fp32 or fp16 C
__device__ __forceinline__ void stpair(float* C, size_t idx, float a, float b) {
    *(float2*)(C + idx) = make_float2(a, b);
}
__device__ __forceinline__ void stpair(__half* C, size_t idx, float a, float b) {
    *(__half2*)(C + idx) = __floats2half2_rn(a, b);
}

// ===========================================================================
// FP16 tensor-core GEMM: C[M,N] = A[M,K] @ Bt[N,K]^T   (both fp16, K-contig)
// 128x128 tile, BK=64, 256 threads (8 warps), warp tile 64x32, m16n8k16.
// Smem rows stride 72 halfs -> fragment LDS bank == lane (conflict-free).
// ===========================================================================
#define HSTR 72
#define HSZ  (128 * HSTR)          // 9216 halfs per tile
#define HGEMM_SMEM (4 * HSZ * 2)   // 73728 B (A x2, B x2)

template <typename CT>
__global__ __launch_bounds__(256) void h16_gemm(
    const __half* __restrict__ A, const __half* __restrict__ Bt,
    CT* __restrict__ C, int M, int N, int K)
{
    extern __shared__ __align__(16) __half sh[];
    __half* As = sh;              // 2 x HSZ
    __half* Bs = sh + 2 * HSZ;    // 2 x HSZ

    const int t    = threadIdx.x;
    const int warp = t >> 5;
    const int lane = t & 31;
    const int r    = lane >> 2;
    const int c    = lane & 3;
    const int wm   = (warp >> 2) * 64;
    const int wn   = (warp & 3) * 32;
    const int bm   = blockIdx.y * 128;
    const int bn   = blockIdx.x * 128;

    // loader mapping: 128 rows x 8 uint4-chunks (64 halfs/row), 4 iters
    const uint4* agp[4];
    const uint4* bgp[4];
    int soff[4];
    #pragma unroll
    for (int i = 0; i < 4; i++) {
        int lin = t + i * 256;
        int row = lin >> 3, ch = lin & 7;
        agp[i] = (const uint4*)(A  + (size_t)(bm + row) * K) + ch;
        bgp[i] = (const uint4*)(Bt + (size_t)(bn + row) * K) + ch;
        soff[i] = row * HSTR + ch * 8;
    }

    const int NKT = K / 64;
    uint4 ra[4], rb[4];

    #pragma unroll
    for (int i = 0; i < 4; i++) { ra[i] = agp[i][0]; rb[i] = bgp[i][0]; }
    #pragma unroll
    for (int i = 0; i < 4; i++) {
        *(uint4*)&As[soff[i]] = ra[i];
        *(uint4*)&Bs[soff[i]] = rb[i];
    }
    __syncthreads();

    float acc[4][4][4];
    #pragma unroll
    for (int mt = 0; mt < 4; mt++)
        #pragma unroll
        for (int nt = 0; nt < 4; nt++)
            #pragma unroll
            for (int x = 0; x < 4; x++) acc[mt][nt][x] = 0.f;

    for (int kt = 0; kt < NKT; kt++) {
        if (kt + 1 < NKT) {
            #pragma unroll
            for (int i = 0; i < 4; i++) {
                ra[i] = agp[i][(kt + 1) * 8];
                rb[i] = bgp[i][(kt + 1) * 8];
            }
        }

        const __half* Ab = As + (kt & 1) * HSZ;
        const __half* Bb = Bs + (kt & 1) * HSZ;

        #pragma unroll
        for (int ks = 0; ks < 4; ks++) {
            unsigned af[4][4], bf[4][2];
            #pragma unroll
            for (int mt = 0; mt < 4; mt++) {
                const __half* p = Ab + (wm + mt * 16 + r) * HSTR + ks * 16 + 2 * c;
                af[mt][0] = ldu32(p);
                af[mt][1] = ldu32(p + 8 * HSTR);
                af[mt][2] = ldu32(p + 8);
                af[mt][3] = ldu32(p + 8 * HSTR + 8);
            }
            #pragma unroll
            for (int nt = 0; nt < 4; nt++) {
                const __half* p = Bb + (wn + nt * 8 + r) * HSTR + ks * 16 + 2 * c;
                bf[nt][0] = ldu32(p);
                bf[nt][1] = ldu32(p + 8);
            }
            #pragma unroll
            for (int mt = 0; mt < 4; mt++)
                #pragma unroll
                for (int nt = 0; nt < 4; nt++)
                    mma_f16(acc[mt][nt], af[mt][0], af[mt][1], af[mt][2], af[mt][3],
                            bf[nt][0], bf[nt][1]);
        }

        if (kt + 1 < NKT) {
            __half* Abn = As + ((kt + 1) & 1) * HSZ;
            __half* Bbn = Bs + ((kt + 1) & 1) * HSZ;
            #pragma unroll
            for (int i = 0; i < 4; i++) {
                *(uint4*)&Abn[soff[i]] = ra[i];
                *(uint4*)&Bbn[soff[i]] = rb[i];
            }
        }
        __syncthreads();
    }

    #pragma unroll
    for (int mt = 0; mt < 4; mt++) {
        const int row0 = bm + wm + mt * 16 + r;
        #pragma unroll
        for (int nt = 0; nt < 4; nt++) {
            const int col = bn + wn + nt * 8 + 2 * c;
            stpair(C, (size_t)row0 * N + col,       acc[mt][nt][0], acc[mt][nt][1]);
            stpair(C, (size_t)(row0 + 8) * N + col, acc[mt][nt][2], acc[mt][nt][3]);
        }
    }
}

// ===========================================================================
// Prep kernels
// ===========================================================================
__global__ void cvt_h(const float* __restrict__ src, __half* __restrict__ dst)
{
    size_t i = (size_t)blockIdx.x * blockDim.x + threadIdx.x;
    float4 v = *(const float4*)(src + i * 4);
    __half2 h0 = __floats2half2_rn(v.x, v.y);
    __half2 h1 = __floats2half2_rn(v.z, v.w);
    uint2 o;
    o.x = *reinterpret_cast<unsigned*>(&h0);
    o.y = *reinterpret_cast<unsigned*>(&h1);
    *(uint2*)(dst + i * 4) = o;
}

// src [K][N] fp32 -> dst [N][K] fp16
__global__ void transpose_h(const float* __restrict__ src, __half* __restrict__ dst,
                            int K, int N)
{
    __shared__ float tile[32][33];
    int x = blockIdx.x * 32 + threadIdx.x;   // n
    int y = blockIdx.y * 32 + threadIdx.y;   // k
    #pragma unroll
    for (int i = 0; i < 32; i += 8)
        tile[threadIdx.y + i][threadIdx.x] = src[(size_t)(y + i) * N + x];
    __syncthreads();
    int x2 = blockIdx.y * 32 + threadIdx.x;  // k
    int y2 = blockIdx.x * 32 + threadIdx.y;  // n
    #pragma unroll
    for (int i = 0; i < 32; i += 8)
        dst[(size_t)(y2 + i) * K + x2] = __float2half_rn(tile[threadIdx.x][threadIdx.y + i]);
}

// g_V [m][kvh*HD+hd] -> g_Vt [b][kvh][hd][s]
__global__ void vtrans_h()
{
    __shared__ __half tile[32][33];
    int b   = blockIdx.z >> 3;
    int kvh = blockIdx.z & 7;
    int x = blockIdx.y * 32 + threadIdx.x;   // hd
    int y = blockIdx.x * 32 + threadIdx.y;   // s
    #pragma unroll
    for (int i = 0; i < 32; i += 8)
        tile[threadIdx.y + i][threadIdx.x] =
            g_V[(size_t)(b * S_ + y + i) * (NKV_ * HD_) + kvh * HD_ + x];
    __syncthreads();
    int x2 = blockIdx.x * 32 + threadIdx.x;  // s
    int y2 = blockIdx.y * 32 + threadIdx.y;  // hd
    #pragma unroll
    for (int i = 0; i < 32; i += 8)
        g_Vt[((size_t)(b * NKV_ + kvh) * HD_ + y2 + i) * S_ + x2] =
            tile[threadIdx.x][threadIdx.y + i];
}

// RoPE in-place on fp16 g_Q, g_K. One thread per half2 pair (2p,2p+1 | +64).
__global__ void rope_h(const int* __restrict__ pos_ids)
{
    const int QP = MROWS * NH_ * 32;    // 4194304
    const int KP = MROWS * NKV_ * 32;   // 1048576
    int idx = blockIdx.x * blockDim.x + threadIdx.x;
    if (idx >= QP + KP) return;

    __half* base;
    int m, p;
    if (idx < QP) {
        m = idx >> 10;
        int rem = idx & 1023;
        base = g_Q + ((size_t)m * NH_ + (rem >> 5)) * HD_;
        p = rem & 31;
    } else {
        int i2 = idx - QP;
        m = i2 >> 8;
        int rem = i2 & 255;
        base = g_K + ((size_t)m * NKV_ + (rem >> 5)) * HD_;
        p = rem & 31;
    }
    float pos = (float)pos_ids[m];
    float i0 = exp2f((float)(2 * p)     * -0.20762050593045857f);
    float i1 = exp2f((float)(2 * p + 1) * -0.20762050593045857f);
    float s0, c0, s1, c1;
    sincosf(pos * i0, &s0, &c0);
    sincosf(pos * i1, &s1, &c1);

    __half2 lo = *(__half2*)(base + 2 * p);
    __half2 hi = *(__half2*)(base + 64 + 2 * p);
    float x00 = __low2float(lo),  x01 = __high2float(lo);
    float x10 = __low2float(hi),  x11 = __high2float(hi);
    *(__half2*)(base + 2 * p)      = __floats2half2_rn(x00 * c0 - x10 * s0,
                                                       x01 * c1 - x11 * s1);
    *(__half2*)(base + 64 + 2 * p) = __floats2half2_rn(x10 * c0 + x00 * s0,
                                                       x11 * c1 + x01 * s1);
}

// ===========================================================================
// FP16 tensor-core flash attention, sliding window 1024, GQA.
// Block = (q_tile 128, head, batch), 256 threads (8 warps x 16 q-rows).
// Qs/Ks [row][136h], Vs [hd][72h], Ps per-warp [16][72h] — all frag LDS
// bank-conflict-free (bank == 4r+c == lane).
// ===========================================================================
#define AQSTR 136
#define AVSTR 72
#define APSTR 72
#define QT_ 128
#define MASKED_ (-30000.0f)
#define MINIT_  (-10000.0f)
#define ATTN_SMEM ((128*AQSTR + 64*AQSTR + 128*AVSTR + 8*16*APSTR) * 2) // 89088 B

__global__ __launch_bounds__(256) void attn_mma_kernel()
{
    extern __shared__ __align__(16) __half sm[];
    __half* Qs = sm;                           // 128*136 = 17408 h
    __half* Ks = sm + 128 * AQSTR;             // 64*136  = 8704 h
    __half* Vs = Ks + 64 * AQSTR;              // 128*72  = 9216 h
    __half* Ps = Vs + 128 * AVSTR;             // 8*16*72 = 9216 h

    const int t     = threadIdx.x;
    const int w     = t >> 5;
    const int lane  = t & 31;
    const int r     = lane >> 2;
    const int c     = lane & 3;
    const int qtile = (int)gridDim.x - 1 - (int)blockIdx.x;   // heavy tiles first
    const int h     = blockIdx.y;
    const int b     = blockIdx.z;
    const int q0    = qtile * QT_;
    const int kvh   = h >> 2;

    __half* Psw = Ps + w * (16 * APSTR);

    // ---- load Q tile ----
    {
        const uint4* Qg4 = (const uint4*)(g_Q + ((size_t)(b * S_ + q0) * NH_ + h) * HD_);
        #pragma unroll
        for (int i = 0; i < 8; i++) {
            int lin = t + i * 256;
            int row = lin >> 4, ch = lin & 15;
            *(uint4*)&Qs[row * AQSTR + ch * 8] = Qg4[row * (NH_ * HD_ / 8) + ch];
        }
    }

    float m0 = MINIT_, m1 = MINIT_, l0 = 0.f, l1 = 0.f;
    float acc[16][4];
    #pragma unroll
    for (int nt = 0; nt < 16; nt++)
        #pragma unroll
        for (int x = 0; x < 4; x++) acc[nt][x] = 0.f;

    const int gi0 = q0 + w * 16 + r;
    const int gi1 = gi0 + 8;
    const int kb_lo = (q0 >= WIN_) ? ((q0 - WIN_) >> 6) : 0;
    const int kb_hi = (q0 + QT_ - 1) >> 6;
    const float scale = 0.08838834764831845f;   // 1/sqrt(128)

    for (int kb = kb_lo; kb <= kb_hi; kb++) {
        __syncthreads();
        // ---- load K (64x128) and V^T (128 hd x 64 keys) ----
        {
            const uint4* Kg4 = (const uint4*)(g_K +
                ((size_t)(b * S_ + kb * 64) * NKV_ + kvh) * HD_);
            const uint4* Vg4 = (const uint4*)(g_Vt +
                ((size_t)(b * NKV_ + kvh) * HD_) * S_ + kb * 64);
            #pragma unroll
            for (int i = 0; i < 4; i++) {
                int lin = t + i * 256;
                int row = lin >> 4, ch = lin & 15;
                *(uint4*)&Ks[row * AQSTR + ch * 8] = Kg4[row * (NKV_ * HD_ / 8) + ch];
                int vrow = lin >> 3, vch = lin & 7;
                *(uint4*)&Vs[vrow * AVSTR + vch * 8] = Vg4[vrow * (S_ / 8) + vch];
            }
        }
        __syncthreads();

        // ---- S = Q @ K^T : per warp 16x64, 8 k-steps of 16 ----
        float s[8][4];
        #pragma unroll
        for (int nt = 0; nt < 8; nt++)
            #pragma unroll
            for (int x = 0; x < 4; x++) s[nt][x] = 0.f;

        #pragma unroll
        for (int ks = 0; ks < 8; ks++) {
            const __half* qp = Qs + (w * 16 + r) * AQSTR + ks * 16 + 2 * c;
            unsigned a0 = ldu32(qp);
            unsigned a1 = ldu32(qp + 8 * AQSTR);
            unsigned a2 = ldu32(qp + 8);
            unsigned a3 = ldu32(qp + 8 * AQSTR + 8);
            #pragma unroll
            for (int nt = 0; nt < 8; nt++) {
                const __half* kp = Ks + (nt * 8 + r) * AQSTR + ks * 16 + 2 * c;
                mma_f16(s[nt], a0, a1, a2, a3, ldu32(kp), ldu32(kp + 8));
            }
        }

        // ---- scale + window mask + row max ----
        float mx0 = MASKED_, mx1 = MASKED_;
        #pragma unroll
        for (int nt = 0; nt < 8; nt++) {
            #pragma unroll
            for (int jj = 0; jj < 2; jj++) {
                int gj = kb * 64 + nt * 8 + 2 * c + jj;
                float v0 = s[nt][jj] * scale;
                v0 = (gj <= gi0 && gj + WIN_ >= gi0) ? v0 : MASKED_;
                s[nt][jj] = v0;
                mx0 = fmaxf(mx0, v0);
                float v1 = s[nt][2 + jj] * scale;
                v1 = (gj <= gi1 && gj + WIN_ >= gi1) ? v1 : MASKED_;
                s[nt][2 + jj] = v1;
                mx1 = fmaxf(mx1, v1);
            }
        }
        mx0 = fmaxf(mx0, __shfl_xor_sync(0xffffffffu, mx0, 1));
        mx0 = fmaxf(mx0, __shfl_xor_sync(0xffffffffu, mx0, 2));
        mx1 = fmaxf(mx1, __shfl_xor_sync(0xffffffffu, mx1, 1));
        mx1 = fmaxf(mx1, __shfl_xor_sync(0xffffffffu, mx1, 2));

        const float mn0 = fmaxf(m0, mx0);
        const float mn1 = fmaxf(m1, mx1);
        const float al0 = __expf(m0 - mn0);
        const float al1 = __expf(m1 - mn1);
        m0 = mn0; m1 = mn1;
        l0 *= al0; l1 *= al1;
        #pragma unroll
        for (int nt = 0; nt < 16; nt++) {
            acc[nt][0] *= al0; acc[nt][1] *= al0;
            acc[nt][2] *= al1; acc[nt][3] *= al1;
        }

        // ---- exp + fp16 P to per-warp smem ----
        float ss0 = 0.f, ss1 = 0.f;
        #pragma unroll
        for (int nt = 0; nt < 8; nt++) {
            __half2 h01 = __floats2half2_rn(__expf(s[nt][0] - mn0),
                                            __expf(s[nt][1] - mn0));
            __half2 h23 = __floats2half2_rn(__expf(s[nt][2] - mn1),
                                            __expf(s[nt][3] - mn1));
            ss0 += __low2float(h01) + __high2float(h01);
            ss1 += __low2float(h23) + __high2float(h23);
            *(__half2*)&Psw[r * APSTR + nt * 8 + 2 * c]       = h01;
            *(__half2*)&Psw[(r + 8) * APSTR + nt * 8 + 2 * c] = h23;
        }
        ss0 += __shfl_xor_sync(0xffffffffu, ss0, 1);
        ss0 += __shfl_xor_sync(0xffffffffu, ss0, 2);
        ss1 += __shfl_xor_sync(0xffffffffu, ss1, 1);
        ss1 += __shfl_xor_sync(0xffffffffu, ss1, 2);
        l0 += ss0; l1 += ss1;

        __syncwarp();

        // ---- O += P @ V : 16 n-tiles x 4 k-steps of 16 ----
        #pragma unroll
        for (int ks = 0; ks < 4; ks++) {
            const __half* pp = Psw + r * APSTR + ks * 16 + 2 * c;
            unsigned a0 = ldu32(pp);
            unsigned a1 = ldu32(pp + 8 * APSTR);
            unsigned a2 = ldu32(pp + 8);
            unsigned a3 = ldu32(pp + 8 * APSTR + 8);
            #pragma unroll
            for (int nt = 0; nt < 16; nt++) {
                const __half* vp = Vs + (nt * 8 + r) * AVSTR + ks * 16 + 2 * c;
                mma_f16(acc[nt], a0, a1, a2, a3, ldu32(vp), ldu32(vp + 8));
            }
        }
    }

    // ---- epilogue: normalized fp16 AO ----
    const float il0 = 1.f / l0;
    const float il1 = 1.f / l1;
    __half* O0 = g_AO + ((size_t)(b * S_ + gi0) * NH_ + h) * HD_;
    __half* O1 = g_AO + ((size_t)(b * S_ + gi1) * NH_ + h) * HD_;
    #pragma unroll
    for (int nt = 0; nt < 16; nt++) {
        int col = nt * 8 + 2 * c;
        *(__half2*)(O0 + col) = __floats2half2_rn(acc[nt][0] * il0, acc[nt][1] * il0);
        *(__half2*)(O1 + col) = __floats2half2_rn(acc[nt][2] * il1, acc[nt][3] * il1);
    }
}

// ===========================================================================
extern "C" void kernel_launch(void* const* d_in, const int* in_sizes, int n_in,
                              void* d_out, int out_size)
{
    (void)in_sizes; (void)n_in; (void)out_size;
    const float* hidden  = (const float*)d_in[0];
    const int*   pos_ids = (const int*)d_in[2];
    const float* q_w     = (const float*)d_in[3];
    const float* k_w     = (const float*)d_in[4];
    const float* v_w     = (const float*)d_in[5];
    const float* o_w     = (const float*)d_in[6];
    float* out = (float*)d_out;

    __half *Hh, *Wq, *Wk, *Wv, *Wo, *Qh, *Kh, *Vh, *AOh;
    cudaGetSymbolAddress((void**)&Hh,  g_Hh);
    cudaGetSymbolAddress((void**)&Wq,  g_Wq);
    cudaGetSymbolAddress((void**)&Wk,  g_Wk);
    cudaGetSymbolAddress((void**)&Wv,  g_Wv);
    cudaGetSymbolAddress((void**)&Wo,  g_Wo);
    cudaGetSymbolAddress((void**)&Qh,  g_Q);
    cudaGetSymbolAddress((void**)&Kh,  g_K);
    cudaGetSymbolAddress((void**)&Vh,  g_V);
    cudaGetSymbolAddress((void**)&AOh, g_AO);

    cudaFuncSetAttribute(h16_gemm<__half>,
        cudaFuncAttributeMaxDynamicSharedMemorySize, HGEMM_SMEM);
    cudaFuncSetAttribute(h16_gemm<float>,
        cudaFuncAttributeMaxDynamicSharedMemorySize, HGEMM_SMEM);
    cudaFuncSetAttribute(attn_mma_kernel,
        cudaFuncAttributeMaxDynamicSharedMemorySize, ATTN_SMEM);

    // Prep: fp16 conversions + weight transposes
    cvt_h<<<(MROWS * HID_ / 4) / 256, 256>>>(hidden, Hh);
    transpose_h<<<dim3(HID_ / 32, HID_ / 32), dim3(32, 8)>>>(q_w, Wq, HID_, HID_);
    transpose_h<<<dim3((NKV_ * HD_) / 32, HID_ / 32), dim3(32, 8)>>>(k_w, Wk, HID_, NKV_ * HD_);
    transpose_h<<<dim3((NKV_ * HD_) / 32, HID_ / 32), dim3(32, 8)>>>(v_w, Wv, HID_, NKV_ * HD_);
    transpose_h<<<dim3(HID_ / 32, HID_ / 32), dim3(32, 8)>>>(o_w, Wo, HID_, HID_);

    // QKV projections (fp16 in/out, fp32 accum)
    h16_gemm<__half><<<dim3(NH_ * HD_ / 128, MROWS / 128), 256, HGEMM_SMEM>>>(
        Hh, Wq, Qh, MROWS, NH_ * HD_, HID_);
    h16_gemm<__half><<<dim3(NKV_ * HD_ / 128, MROWS / 128), 256, HGEMM_SMEM>>>(
        Hh, Wk, Kh, MROWS, NKV_ * HD_, HID_);
    h16_gemm<__half><<<dim3(NKV_ * HD_ / 128, MROWS / 128), 256, HGEMM_SMEM>>>(
        Hh, Wv, Vh, MROWS, NKV_ * HD_, HID_);

    // RoPE (fp16 in-place) + V transpose
    {
        int total = MROWS * NH_ * 32 + MROWS * NKV_ * 32;
        rope_h<<<(total + 255) / 256, 256>>>(pos_ids);
    }
    vtrans_h<<<dim3(S_ / 32, HD_ / 32, B_ * NKV_), dim3(32, 8)>>>();

    // Attention
    attn_mma_kernel<<<dim3(S_ / QT_, NH_, B_), 256, ATTN_SMEM>>>();

    // Output projection (fp16 A/B, fp32 out)
    h16_gemm<float><<<dim3(HID_ / 128, MROWS / 128), 256, HGEMM_SMEM>>>(
        AOh, Wo, out, MROWS, HID_, HID_);
}